// round 4
// baseline (speedup 1.0000x reference)
#include <cuda_runtime.h>
#include <math.h>

#define BB 8
#define TT 4096
#define DD 512
#define VV 50257
#define NSLOTS 256
#define KWIN 8
#define NTOK (BB*TT)          // 32768

// ---------------- scratch (device globals; no allocation) ----------------
__device__ float g_h0[(size_t)NTOK*DD];        // 67 MB
__device__ float g_a1[(size_t)NTOK*2*DD];      // 134 MB
__device__ float g_ff[(size_t)NTOK*DD];        // 67 MB
__device__ float g_h [(size_t)NTOK*DD];        // 67 MB
__device__ float g_u[NTOK];
__device__ float g_v[NTOK];
__device__ float g_gate[NTOK];
__device__ int   g_top[BB*NSLOTS];
__device__ float g_q[BB*DD];
__device__ float g_ctx[BB*DD];

// ---------------- embedding gather ----------------
__global__ void gather_kernel(const int* __restrict__ seq,
                              const float* __restrict__ embed) {
    long i = (long)blockIdx.x * blockDim.x + threadIdx.x;   // over NTOK * D/4
    long total = (long)NTOK * (DD/4);
    if (i >= total) return;
    int tokpos = (int)(i / (DD/4));
    int dc     = (int)(i % (DD/4));
    int tok = seq[tokpos];
    ((float4*)g_h0)[(long)tokpos*(DD/4) + dc] =
        ((const float4*)embed)[(long)tok*(DD/4) + dc];
}

// ---------------- SGEMM 128x128x8, 256 threads, 8x8/thread, double-buffered ----
// C[M,N] = act(A[M,K] @ B[K,N] + bias[N]); ACT=1 -> relu
template<int ACT>
__global__ void __launch_bounds__(256)
sgemm_kernel(const float* __restrict__ A, const float* __restrict__ B,
             const float* __restrict__ bias, float* __restrict__ C,
             int M, int N, int K) {
    __shared__ float As[2][8][128];
    __shared__ float Bs[2][8][128];
    int tid = threadIdx.x;
    int bx = blockIdx.x;          // N tile
    int by = blockIdx.y;          // M tile
    int tx = tid % 16;            // 16 thread-cols
    int ty = tid / 16;            // 16 thread-rows

    int aRow = tid >> 1;          // 0..127
    int aCol = (tid & 1) * 4;     // 0 or 4
    int bRow = tid >> 5;          // 0..7
    int bCol = (tid & 31) * 4;    // 0..124

    const float* Ab = A + (long)(by * 128) * K;
    const float* Bb = B + bx * 128;

    float acc[8][8];
    #pragma unroll
    for (int i = 0; i < 8; i++)
        #pragma unroll
        for (int j = 0; j < 8; j++) acc[i][j] = 0.f;

    // preload first K-slice into buffer 0
    float4 a4 = *(const float4*)(Ab + (long)aRow * K + aCol);
    float4 b4 = *(const float4*)(Bb + (long)bRow * N + bCol);
    As[0][aCol+0][aRow] = a4.x; As[0][aCol+1][aRow] = a4.y;
    As[0][aCol+2][aRow] = a4.z; As[0][aCol+3][aRow] = a4.w;
    *(float4*)&Bs[0][bRow][bCol] = b4;
    __syncthreads();

    int nk = K >> 3;
    for (int kt = 0; kt < nk; kt++) {
        int buf = kt & 1;
        // prefetch next slice into registers (overlaps with compute below)
        if (kt + 1 < nk) {
            a4 = *(const float4*)(Ab + (long)aRow * K + (kt + 1) * 8 + aCol);
            b4 = *(const float4*)(Bb + (long)((kt + 1) * 8 + bRow) * N + bCol);
        }
        #pragma unroll
        for (int kk = 0; kk < 8; kk++) {
            float ar[8], br[8];
            #pragma unroll
            for (int i = 0; i < 8; i++) ar[i] = As[buf][kk][ty*8 + i];
            #pragma unroll
            for (int j = 0; j < 8; j++) br[j] = Bs[buf][kk][tx*8 + j];
            #pragma unroll
            for (int i = 0; i < 8; i++)
                #pragma unroll
                for (int j = 0; j < 8; j++) acc[i][j] += ar[i] * br[j];
        }
        if (kt + 1 < nk) {
            int nb = buf ^ 1;
            As[nb][aCol+0][aRow] = a4.x; As[nb][aCol+1][aRow] = a4.y;
            As[nb][aCol+2][aRow] = a4.z; As[nb][aCol+3][aRow] = a4.w;
            *(float4*)&Bs[nb][bRow][bCol] = b4;
            __syncthreads();
        }
    }
    #pragma unroll
    for (int i = 0; i < 8; i++) {
        int row = by*128 + ty*8 + i;
        #pragma unroll
        for (int j = 0; j < 8; j++) {
            int col = bx*128 + tx*8 + j;
            float vv = acc[i][j] + bias[col];
            if (ACT) vv = fmaxf(vv, 0.f);
            C[(long)row * N + col] = vv;
        }
    }
}

// ---------------- block reduce helper ----------------
__device__ __forceinline__ float block_reduce_sum(float v, float* red) {
    int tid = threadIdx.x;
    #pragma unroll
    for (int o = 16; o > 0; o >>= 1) v += __shfl_down_sync(0xffffffffu, v, o);
    if ((tid & 31) == 0) red[tid >> 5] = v;
    __syncthreads();
    int nw = blockDim.x >> 5;
    if (tid < 32) {
        float x = (tid < nw) ? red[tid] : 0.f;
        #pragma unroll
        for (int o = 16; o > 0; o >>= 1) x += __shfl_down_sync(0xffffffffu, x, o);
        if (tid == 0) red[0] = x;
    }
    __syncthreads();
    float r = red[0];
    __syncthreads();
    return r;
}

// ---------------- layernorm(h0 + ff) ----------------
__global__ void __launch_bounds__(256)
ln_kernel(const float* __restrict__ g, const float* __restrict__ b) {
    __shared__ float red[32];
    int row = blockIdx.x;
    int tid = threadIdx.x;
    long base = (long)row * DD;
    float x1 = g_h0[base + tid]       + g_ff[base + tid];
    float x2 = g_h0[base + tid + 256] + g_ff[base + tid + 256];
    float mean = block_reduce_sum(x1 + x2, red) * (1.f / DD);
    float d1 = x1 - mean, d2 = x2 - mean;
    float var = block_reduce_sum(d1*d1 + d2*d2, red) * (1.f / DD);
    float rstd = rsqrtf(var + 1e-5f);
    g_h[base + tid]       = d1 * rstd * g[tid]       + b[tid];
    g_h[base + tid + 256] = d2 * rstd * g[tid + 256] + b[tid + 256];
}

// ---------------- gate projections: u = h.gW[:D], v = h.gW[D:] ----------------
__global__ void __launch_bounds__(256)
gatedot_kernel(const float* __restrict__ gW) {
    int wid  = threadIdx.x >> 5;
    int lane = threadIdx.x & 31;
    int row = blockIdx.x * 8 + wid;
    if (row >= NTOK) return;
    long base = (long)row * DD;
    float su = 0.f, sv = 0.f;
    for (int d = lane; d < DD; d += 32) {
        float hv = g_h[base + d];
        su += hv * gW[d];
        sv += hv * gW[DD + d];
    }
    #pragma unroll
    for (int o = 16; o > 0; o >>= 1) {
        su += __shfl_down_sync(0xffffffffu, su, o);
        sv += __shfl_down_sync(0xffffffffu, sv, o);
    }
    if (lane == 0) { g_u[row] = su; g_v[row] = sv; }
}

// ---------------- gate = sigmoid(u + windowed-mean(v) + gb) ----------------
__global__ void gatecomb_kernel(const float* __restrict__ gb) {
    int i = blockIdx.x * blockDim.x + threadIdx.x;
    if (i >= NTOK) return;
    int t = i % TT;
    int bstart = i - t;
    int s = min(t + 1, TT);
    int e = min(t + 1 + KWIN, TT);
    int cnt = e - s;
    float fsum = 0.f;
    for (int j = s; j < e; j++) fsum += g_v[bstart + j];
    float fut = (cnt > 0) ? fsum / (float)cnt : 0.f;
    float logit = g_u[i] + fut + gb[0];
    g_gate[i] = 1.f / (1.f + expf(-logit));
}

// ---------------- top-256 per batch via bitonic sort (descending) ----------------
__global__ void __launch_bounds__(512)
topk_kernel() {
    __shared__ float vals[TT];
    __shared__ int   idxs[TT];
    int b = blockIdx.x;
    int tid = threadIdx.x;
    for (int i = tid; i < TT; i += 512) {
        vals[i] = g_gate[b * TT + i];
        idxs[i] = i;
    }
    __syncthreads();
    for (int k = 2; k <= TT; k <<= 1) {
        for (int j = k >> 1; j > 0; j >>= 1) {
            for (int i = tid; i < TT; i += 512) {
                int ixj = i ^ j;
                if (ixj > i) {
                    bool desc = ((i & k) == 0);
                    float vi = vals[i], vx = vals[ixj];
                    bool swap = desc ? (vi < vx) : (vi > vx);
                    if (swap) {
                        vals[i] = vx; vals[ixj] = vi;
                        int t = idxs[i]; idxs[i] = idxs[ixj]; idxs[ixj] = t;
                    }
                }
            }
            __syncthreads();
        }
    }
    for (int m = tid; m < NSLOTS; m += 512)
        g_top[b * NSLOTS + m] = idxs[m];
}

// ---------------- q = h[:, -1, :] @ q_W + q_b ----------------
__global__ void __launch_bounds__(256)
q_kernel(const float* __restrict__ qW, const float* __restrict__ qb) {
    __shared__ float hl[DD];
    int b = blockIdx.x;
    int tid = threadIdx.x;
    long base = ((long)b * TT + (TT - 1)) * DD;
    for (int d = tid; d < DD; d += 256) hl[d] = g_h[base + d];
    __syncthreads();
    for (int j = tid; j < DD; j += 256) {
        float s = qb[j];
        for (int d = 0; d < DD; d++) s += hl[d] * qW[(long)d * DD + j];
        g_q[b * DD + j] = s;
    }
}

// ---------------- scores -> softmax -> ctx ----------------
__global__ void __launch_bounds__(256)
attn_kernel() {
    __shared__ float qs[DD];
    __shared__ float sc[NSLOTS];
    __shared__ int   rows[NSLOTS];
    __shared__ float red[32];
    int b = blockIdx.x;
    int tid = threadIdx.x;
    int wid = tid >> 5, lane = tid & 31;
    for (int d = tid; d < DD; d += 256) qs[d] = g_q[b * DD + d];
    for (int m = tid; m < NSLOTS; m += 256) rows[m] = b * TT + g_top[b * NSLOTS + m];
    __syncthreads();
    // scores: warp-cooperative dots
    for (int m = wid; m < NSLOTS; m += 8) {
        long base = (long)rows[m] * DD;
        float s = 0.f;
        for (int d = lane; d < DD; d += 32) s += g_h[base + d] * qs[d];
        #pragma unroll
        for (int o = 16; o > 0; o >>= 1) s += __shfl_down_sync(0xffffffffu, s, o);
        if (lane == 0) sc[m] = s;
    }
    __syncthreads();
    // softmax over 256
    float v = (tid < NSLOTS) ? sc[tid] : -1e30f;
    float vm = v;
    #pragma unroll
    for (int o = 16; o > 0; o >>= 1) vm = fmaxf(vm, __shfl_down_sync(0xffffffffu, vm, o));
    if ((tid & 31) == 0) red[tid >> 5] = vm;
    __syncthreads();
    if (tid < 32) {
        float x = (tid < 8) ? red[tid] : -1e30f;
        #pragma unroll
        for (int o = 16; o > 0; o >>= 1) x = fmaxf(x, __shfl_down_sync(0xffffffffu, x, o));
        if (tid == 0) red[0] = x;
    }
    __syncthreads();
    float mx = red[0];
    __syncthreads();
    float e = (tid < NSLOTS) ? expf(v - mx) : 0.f;
    float tot = block_reduce_sum(e, red);
    if (tid < NSLOTS) sc[tid] = e / tot;
    __syncthreads();
    // ctx
    for (int d = tid; d < DD; d += 256) {
        float s = 0.f;
        for (int m = 0; m < NSLOTS; m++)
            s += sc[m] * g_h[(long)rows[m] * DD + d];
        g_ctx[b * DD + d] = s;
    }
}

// ---------------- out = ctx @ out_W + out_b ----------------
__global__ void __launch_bounds__(256)
out_kernel(const float* __restrict__ oW, const float* __restrict__ ob,
           float* __restrict__ out) {
    __shared__ float cs[BB * DD];   // 16KB
    int tid = threadIdx.x;
    for (int i = tid; i < BB * DD; i += 256) cs[i] = g_ctx[i];
    __syncthreads();
    int v = blockIdx.x * 256 + tid;
    if (v >= VV) return;
    float acc[BB];
    #pragma unroll
    for (int b = 0; b < BB; b++) acc[b] = 0.f;
    for (int d = 0; d < DD; d++) {
        float w = oW[(long)d * VV + v];
        #pragma unroll
        for (int b = 0; b < BB; b++) acc[b] += cs[b * DD + d] * w;
    }
    float bias = ob[v];
    #pragma unroll
    for (int b = 0; b < BB; b++) out[(long)b * VV + v] = acc[b] + bias;
}

// ---------------- launch ----------------
extern "C" void kernel_launch(void* const* d_in, const int* in_sizes, int n_in,
                              void* d_out, int out_size) {
    const int*   seq   = (const int*)  d_in[0];
    const float* embed = (const float*)d_in[1];
    const float* W1    = (const float*)d_in[2];
    const float* b1    = (const float*)d_in[3];
    const float* W2    = (const float*)d_in[4];
    const float* b2    = (const float*)d_in[5];
    const float* ln_g  = (const float*)d_in[6];
    const float* ln_b  = (const float*)d_in[7];
    const float* gW    = (const float*)d_in[8];
    const float* gb    = (const float*)d_in[9];
    const float* qW    = (const float*)d_in[10];
    const float* qb    = (const float*)d_in[11];
    const float* oW    = (const float*)d_in[12];
    const float* ob    = (const float*)d_in[13];
    float* out = (float*)d_out;

    float *h0, *a1, *ff;
    cudaGetSymbolAddress((void**)&h0, g_h0);
    cudaGetSymbolAddress((void**)&a1, g_a1);
    cudaGetSymbolAddress((void**)&ff, g_ff);

    // 1. embedding gather
    {
        long total = (long)NTOK * (DD / 4);
        int blocks = (int)((total + 255) / 256);
        gather_kernel<<<blocks, 256>>>(seq, embed);
    }
    // 2. GEMM1: a1 = relu(h0 @ W1 + b1)   (M=32768, N=1024, K=512)
    {
        dim3 grid(2 * DD / 128, NTOK / 128);
        sgemm_kernel<1><<<grid, 256>>>(h0, W1, b1, a1, NTOK, 2 * DD, DD);
    }
    // 3. GEMM2: ff = a1 @ W2 + b2          (M=32768, N=512, K=1024)
    {
        dim3 grid(DD / 128, NTOK / 128);
        sgemm_kernel<0><<<grid, 256>>>(a1, W2, b2, ff, NTOK, DD, 2 * DD);
    }
    // 4. h = LN(h0 + ff)
    ln_kernel<<<NTOK, 256>>>(ln_g, ln_b);
    // 5. gate projections + windowed combine
    gatedot_kernel<<<NTOK / 8, 256>>>(gW);
    gatecomb_kernel<<<NTOK / 256, 256>>>(gb);
    // 6. top-256 per batch
    topk_kernel<<<BB, 512>>>();
    // 7. q projection
    q_kernel<<<BB, 256>>>(qW, qb);
    // 8. attention read
    attn_kernel<<<BB, 256>>>();
    // 9. vocab projection
    out_kernel<<<(VV + 255) / 256, 256>>>(oW, ob, out);

    (void)in_sizes; (void)n_in; (void)out_size;
}

// round 6
// speedup vs baseline: 1.9523x; 1.9523x over previous
#include <cuda_runtime.h>
#include <cuda_bf16.h>
#include <math.h>
#include <stdint.h>

#define BB 8
#define TT 4096
#define DD 512
#define VV 50257
#define NSLOTS 256
#define KWIN 8
#define NTOK (BB*TT)          // 32768

// ---------------- scratch (device globals; no allocation) ----------------
__device__ float g_h0[(size_t)NTOK*DD];                 // 67 MB (fp32, for LN residual)
__device__ __nv_bfloat16 g_h0h[(size_t)NTOK*DD];        // 33.5 MB
__device__ __nv_bfloat16 g_h0l[(size_t)NTOK*DD];        // 33.5 MB
__device__ __nv_bfloat16 g_a1h[(size_t)NTOK*2*DD];      // 67 MB
__device__ __nv_bfloat16 g_a1l[(size_t)NTOK*2*DD];      // 67 MB
__device__ float g_ff[(size_t)NTOK*DD];                 // 67 MB
__device__ float g_h [(size_t)NTOK*DD];                 // 67 MB
__device__ __nv_bfloat16 g_w1th[(size_t)2*DD*DD];       // W1^T hi [1024][512]
__device__ __nv_bfloat16 g_w1tl[(size_t)2*DD*DD];
__device__ __nv_bfloat16 g_w2th[(size_t)DD*2*DD];       // W2^T hi [512][1024]
__device__ __nv_bfloat16 g_w2tl[(size_t)DD*2*DD];
__device__ float g_u[NTOK];
__device__ float g_v[NTOK];
__device__ float g_gate[NTOK];
__device__ int   g_top[BB*NSLOTS];
__device__ float g_q[BB*DD];
__device__ float g_ctx[BB*DD];

// ======================= helpers =======================
__device__ __forceinline__ uint32_t smem_to_u32(const void* p) {
    uint32_t a;
    asm("{ .reg .u64 t; cvta.to.shared.u64 t, %1; cvt.u32.u64 %0, t; }" : "=r"(a) : "l"(p));
    return a;
}
__device__ __forceinline__ void bsplit(float x, __nv_bfloat16& h, __nv_bfloat16& l) {
    h = __float2bfloat16_rn(x);
    l = __float2bfloat16_rn(x - __bfloat162float(h));
}
__device__ __forceinline__ void ldm_x4(uint32_t& r0, uint32_t& r1, uint32_t& r2, uint32_t& r3,
                                       uint32_t addr) {
    asm volatile("ldmatrix.sync.aligned.m8n8.x4.shared.b16 {%0,%1,%2,%3}, [%4];"
        : "=r"(r0), "=r"(r1), "=r"(r2), "=r"(r3) : "r"(addr));
}
__device__ __forceinline__ void mma_bf16(float* c, const uint32_t* a, const uint32_t* b) {
    asm volatile("mma.sync.aligned.m16n8k16.row.col.f32.bf16.bf16.f32 "
        "{%0,%1,%2,%3}, {%4,%5,%6,%7}, {%8,%9}, {%0,%1,%2,%3};"
        : "+f"(c[0]), "+f"(c[1]), "+f"(c[2]), "+f"(c[3])
        : "r"(a[0]), "r"(a[1]), "r"(a[2]), "r"(a[3]), "r"(b[0]), "r"(b[1]));
}

// ---------------- weight transpose + bf16 split ----------------
// src fp32 [R][C] -> dsth/dstl bf16 [C][R]
__global__ void transpose_convert_kernel(const float* __restrict__ src,
                                         __nv_bfloat16* __restrict__ dh,
                                         __nv_bfloat16* __restrict__ dl,
                                         int R, int C) {
    __shared__ float t[32][33];
    int bx = blockIdx.x * 32, by = blockIdx.y * 32;
    int x = bx + threadIdx.x;
    #pragma unroll
    for (int j = 0; j < 32; j += 8) {
        int y = by + threadIdx.y + j;
        t[threadIdx.y + j][threadIdx.x] = src[(size_t)y * C + x];
    }
    __syncthreads();
    int xo = by + threadIdx.x;
    #pragma unroll
    for (int j = 0; j < 32; j += 8) {
        int yo = bx + threadIdx.y + j;
        float v = t[threadIdx.x][threadIdx.y + j];
        __nv_bfloat16 h, l; bsplit(v, h, l);
        dh[(size_t)yo * R + xo] = h;
        dl[(size_t)yo * R + xo] = l;
    }
}

// ---------------- embedding gather + bf16 split ----------------
__global__ void gather_kernel(const int* __restrict__ seq,
                              const float* __restrict__ embed) {
    long i = (long)blockIdx.x * blockDim.x + threadIdx.x;   // over NTOK * 128
    long total = (long)NTOK * (DD/4);
    if (i >= total) return;
    int tokpos = (int)(i >> 7);
    int dc     = (int)(i & 127);
    int tok = seq[tokpos];
    float4 e = ((const float4*)embed)[(long)tok * 128 + dc];
    ((float4*)g_h0)[i] = e;
    __nv_bfloat16 hx, lx, hy, ly, hz, lz, hw, lw;
    bsplit(e.x, hx, lx); bsplit(e.y, hy, ly);
    bsplit(e.z, hz, lz); bsplit(e.w, hw, lw);
    __nv_bfloat162* ph = (__nv_bfloat162*)g_h0h + i * 2;
    __nv_bfloat162* pl = (__nv_bfloat162*)g_h0l + i * 2;
    ph[0] = __nv_bfloat162{hx, hy}; ph[1] = __nv_bfloat162{hz, hw};
    pl[0] = __nv_bfloat162{lx, ly}; pl[1] = __nv_bfloat162{lz, lw};
}

// ============== mma.sync bf16 3-pass split GEMM ==============
// C = act(A @ Bt^T + bias); A [M][K], Bt [N][K] (both bf16 hi/lo, K-major)
// CTA tile 128x128, 8 warps (2m x 4n), warp tile 64x32, K-chunk 16, double-buffered.
// EPI=1: relu -> write bf16 hi/lo (Ch, Cl). EPI=0: write fp32 Cf.
#define SPITCH 24                       // bf16 elems per smem row (48B, conflict-free ldmatrix)
#define STILE  (128 * SPITCH * 2)       // 6144 bytes per tile
#define GEMM_SMEM (8 * STILE)           // 49152 (<= default 48KB dyn limit)

template<int EPI>
__global__ void __launch_bounds__(256)
mma_gemm_kernel(const __nv_bfloat16* __restrict__ Ah, const __nv_bfloat16* __restrict__ Al,
                const __nv_bfloat16* __restrict__ Bh, const __nv_bfloat16* __restrict__ Bl,
                const float* __restrict__ bias,
                float* __restrict__ Cf,
                __nv_bfloat16* __restrict__ Ch, __nv_bfloat16* __restrict__ Cl,
                int M, int N, int K) {
    extern __shared__ char smem[];
    uint32_t sb = smem_to_u32(smem);
    int tid = threadIdx.x;
    int lane = tid & 31, wid = tid >> 5;
    int wm = wid >> 2, wn = wid & 3;            // 2 x 4 warp grid
    int bx = blockIdx.x, by = blockIdx.y;

    // global load mapping: 256 threads, each 16B per array per chunk
    int grow = tid >> 1;                        // 0..127
    int ghalf = tid & 1;                        // 0..1  (16B halves of a 32B row-chunk)
    const __nv_bfloat16* pAh = Ah + (size_t)(by * 128 + grow) * K + ghalf * 8;
    const __nv_bfloat16* pAl = Al + (size_t)(by * 128 + grow) * K + ghalf * 8;
    const __nv_bfloat16* pBh = Bh + (size_t)(bx * 128 + grow) * K + ghalf * 8;
    const __nv_bfloat16* pBl = Bl + (size_t)(bx * 128 + grow) * K + ghalf * 8;
    uint32_t sdst = (uint32_t)(grow * 48 + ghalf * 16);   // byte offset within tile

    // smem tile bases: arr 0=Ah 1=Al 2=Bh 3=Bl, buf in {0,1}
    #define TBASE(arr, buf) ((uint32_t)((arr) * 2 * STILE + (buf) * STILE))

    float acc[4][4][4];
    #pragma unroll
    for (int i = 0; i < 4; i++)
        #pragma unroll
        for (int j = 0; j < 4; j++)
            #pragma unroll
            for (int r = 0; r < 4; r++) acc[i][j][r] = 0.f;

    // ldmatrix per-warp byte offsets (within a tile)
    uint32_t a_off = (uint32_t)((wm * 64 + (lane & 15)) * 48 + (lane >> 4) * 16);
    uint32_t b_off = (uint32_t)((wn * 32 + (lane & 7) + ((lane >> 4) << 3)) * 48
                                + ((lane >> 3) & 1) * 16);

    int nk = K >> 4;
    // preload chunk 0 into buf 0
    {
        *(uint4*)(smem + TBASE(0,0) + sdst) = *(const uint4*)(pAh);
        *(uint4*)(smem + TBASE(1,0) + sdst) = *(const uint4*)(pAl);
        *(uint4*)(smem + TBASE(2,0) + sdst) = *(const uint4*)(pBh);
        *(uint4*)(smem + TBASE(3,0) + sdst) = *(const uint4*)(pBl);
    }
    __syncthreads();

    for (int c = 0; c < nk; c++) {
        int buf = c & 1;
        uint4 vAh, vAl, vBh, vBl;
        if (c + 1 < nk) {
            int ko = (c + 1) * 16;
            vAh = *(const uint4*)(pAh + ko);
            vAl = *(const uint4*)(pAl + ko);
            vBh = *(const uint4*)(pBh + ko);
            vBl = *(const uint4*)(pBl + ko);
        }
        uint32_t sA_h = sb + TBASE(0, buf), sA_l = sb + TBASE(1, buf);
        uint32_t sB_h = sb + TBASE(2, buf), sB_l = sb + TBASE(3, buf);

        uint32_t a[4][4], b[4][2];
        // ---- pass hh: A_hi x B_hi ----
        #pragma unroll
        for (int mt = 0; mt < 4; mt++)
            ldm_x4(a[mt][0], a[mt][1], a[mt][2], a[mt][3], sA_h + a_off + mt * 768);
        #pragma unroll
        for (int p = 0; p < 2; p++)
            ldm_x4(b[2*p][0], b[2*p][1], b[2*p+1][0], b[2*p+1][1], sB_h + b_off + p * 768);
        #pragma unroll
        for (int mt = 0; mt < 4; mt++)
            #pragma unroll
            for (int nt = 0; nt < 4; nt++) mma_bf16(acc[mt][nt], a[mt], b[nt]);
        // ---- pass hl: A_hi x B_lo ----
        #pragma unroll
        for (int p = 0; p < 2; p++)
            ldm_x4(b[2*p][0], b[2*p][1], b[2*p+1][0], b[2*p+1][1], sB_l + b_off + p * 768);
        #pragma unroll
        for (int mt = 0; mt < 4; mt++)
            #pragma unroll
            for (int nt = 0; nt < 4; nt++) mma_bf16(acc[mt][nt], a[mt], b[nt]);
        // ---- pass lh: A_lo x B_hi ----
        #pragma unroll
        for (int mt = 0; mt < 4; mt++)
            ldm_x4(a[mt][0], a[mt][1], a[mt][2], a[mt][3], sA_l + a_off + mt * 768);
        #pragma unroll
        for (int p = 0; p < 2; p++)
            ldm_x4(b[2*p][0], b[2*p][1], b[2*p+1][0], b[2*p+1][1], sB_h + b_off + p * 768);
        #pragma unroll
        for (int mt = 0; mt < 4; mt++)
            #pragma unroll
            for (int nt = 0; nt < 4; nt++) mma_bf16(acc[mt][nt], a[mt], b[nt]);

        if (c + 1 < nk) {
            int nb = buf ^ 1;
            *(uint4*)(smem + TBASE(0,nb) + sdst) = vAh;
            *(uint4*)(smem + TBASE(1,nb) + sdst) = vAl;
            *(uint4*)(smem + TBASE(2,nb) + sdst) = vBh;
            *(uint4*)(smem + TBASE(3,nb) + sdst) = vBl;
        }
        __syncthreads();
    }

    // ---- epilogue ----
    int m_base = by * 128 + wm * 64;
    int n_base = bx * 128 + wn * 32;
    #pragma unroll
    for (int mt = 0; mt < 4; mt++) {
        #pragma unroll
        for (int nt = 0; nt < 4; nt++) {
            int n0 = n_base + nt * 8 + (lane & 3) * 2;
            float bs0 = bias[n0], bs1 = bias[n0 + 1];
            #pragma unroll
            for (int half = 0; half < 2; half++) {
                int m = m_base + mt * 16 + (lane >> 2) + half * 8;
                float v0 = acc[mt][nt][half * 2 + 0] + bs0;
                float v1 = acc[mt][nt][half * 2 + 1] + bs1;
                if (EPI) {
                    v0 = fmaxf(v0, 0.f); v1 = fmaxf(v1, 0.f);
                    __nv_bfloat16 h0, l0, h1, l1;
                    bsplit(v0, h0, l0); bsplit(v1, h1, l1);
                    *(__nv_bfloat162*)(Ch + (size_t)m * N + n0) = __nv_bfloat162{h0, h1};
                    *(__nv_bfloat162*)(Cl + (size_t)m * N + n0) = __nv_bfloat162{l0, l1};
                } else {
                    *(float2*)(Cf + (size_t)m * N + n0) = float2{v0, v1};
                }
            }
        }
    }
    #undef TBASE
}

// ---------------- block reduce helper ----------------
__device__ __forceinline__ float block_reduce_sum(float v, float* red) {
    int tid = threadIdx.x;
    #pragma unroll
    for (int o = 16; o > 0; o >>= 1) v += __shfl_down_sync(0xffffffffu, v, o);
    if ((tid & 31) == 0) red[tid >> 5] = v;
    __syncthreads();
    int nw = blockDim.x >> 5;
    if (tid < 32) {
        float x = (tid < nw) ? red[tid] : 0.f;
        #pragma unroll
        for (int o = 16; o > 0; o >>= 1) x += __shfl_down_sync(0xffffffffu, x, o);
        if (tid == 0) red[0] = x;
    }
    __syncthreads();
    float r = red[0];
    __syncthreads();
    return r;
}

// ---------------- layernorm(h0 + ff) ----------------
__global__ void __launch_bounds__(256)
ln_kernel(const float* __restrict__ g, const float* __restrict__ b) {
    __shared__ float red[32];
    int row = blockIdx.x;
    int tid = threadIdx.x;
    long base = (long)row * DD;
    float x1 = g_h0[base + tid]       + g_ff[base + tid];
    float x2 = g_h0[base + tid + 256] + g_ff[base + tid + 256];
    float mean = block_reduce_sum(x1 + x2, red) * (1.f / DD);
    float d1 = x1 - mean, d2 = x2 - mean;
    float var = block_reduce_sum(d1*d1 + d2*d2, red) * (1.f / DD);
    float rstd = rsqrtf(var + 1e-5f);
    g_h[base + tid]       = d1 * rstd * g[tid]       + b[tid];
    g_h[base + tid + 256] = d2 * rstd * g[tid + 256] + b[tid + 256];
}

// ---------------- gate projections: u = h.gW[:D], v = h.gW[D:] ----------------
__global__ void __launch_bounds__(256)
gatedot_kernel(const float* __restrict__ gW) {
    int wid  = threadIdx.x >> 5;
    int lane = threadIdx.x & 31;
    int row = blockIdx.x * 8 + wid;
    if (row >= NTOK) return;
    long base = (long)row * DD;
    float su = 0.f, sv = 0.f;
    for (int d = lane; d < DD; d += 32) {
        float hv = g_h[base + d];
        su += hv * gW[d];
        sv += hv * gW[DD + d];
    }
    #pragma unroll
    for (int o = 16; o > 0; o >>= 1) {
        su += __shfl_down_sync(0xffffffffu, su, o);
        sv += __shfl_down_sync(0xffffffffu, sv, o);
    }
    if (lane == 0) { g_u[row] = su; g_v[row] = sv; }
}

// ---------------- gate = sigmoid(u + windowed-mean(v) + gb) ----------------
__global__ void gatecomb_kernel(const float* __restrict__ gb) {
    int i = blockIdx.x * blockDim.x + threadIdx.x;
    if (i >= NTOK) return;
    int t = i % TT;
    int bstart = i - t;
    int s = min(t + 1, TT);
    int e = min(t + 1 + KWIN, TT);
    int cnt = e - s;
    float fsum = 0.f;
    for (int j = s; j < e; j++) fsum += g_v[bstart + j];
    float fut = (cnt > 0) ? fsum / (float)cnt : 0.f;
    float logit = g_u[i] + fut + gb[0];
    g_gate[i] = 1.f / (1.f + expf(-logit));
}

// ---------------- top-256 per batch via bitonic sort (descending) ----------------
__global__ void __launch_bounds__(512)
topk_kernel() {
    __shared__ float vals[TT];
    __shared__ int   idxs[TT];
    int b = blockIdx.x;
    int tid = threadIdx.x;
    for (int i = tid; i < TT; i += 512) {
        vals[i] = g_gate[b * TT + i];
        idxs[i] = i;
    }
    __syncthreads();
    for (int k = 2; k <= TT; k <<= 1) {
        for (int j = k >> 1; j > 0; j >>= 1) {
            for (int i = tid; i < TT; i += 512) {
                int ixj = i ^ j;
                if (ixj > i) {
                    bool desc = ((i & k) == 0);
                    float vi = vals[i], vx = vals[ixj];
                    bool swap = desc ? (vi < vx) : (vi > vx);
                    if (swap) {
                        vals[i] = vx; vals[ixj] = vi;
                        int t = idxs[i]; idxs[i] = idxs[ixj]; idxs[ixj] = t;
                    }
                }
            }
            __syncthreads();
        }
    }
    for (int m = tid; m < NSLOTS; m += 512)
        g_top[b * NSLOTS + m] = idxs[m];
}

// ---------------- q = h[:, -1, :] @ q_W + q_b ----------------
__global__ void __launch_bounds__(256)
q_kernel(const float* __restrict__ qW, const float* __restrict__ qb) {
    __shared__ float hl[DD];
    int b = blockIdx.x;
    int tid = threadIdx.x;
    long base = ((long)b * TT + (TT - 1)) * DD;
    for (int d = tid; d < DD; d += 256) hl[d] = g_h[base + d];
    __syncthreads();
    for (int j = tid; j < DD; j += 256) {
        float s = qb[j];
        for (int d = 0; d < DD; d++) s += hl[d] * qW[(long)d * DD + j];
        g_q[b * DD + j] = s;
    }
}

// ---------------- scores -> softmax -> ctx ----------------
__global__ void __launch_bounds__(256)
attn_kernel() {
    __shared__ float qs[DD];
    __shared__ float sc[NSLOTS];
    __shared__ int   rows[NSLOTS];
    __shared__ float red[32];
    int b = blockIdx.x;
    int tid = threadIdx.x;
    int wid = tid >> 5, lane = tid & 31;
    for (int d = tid; d < DD; d += 256) qs[d] = g_q[b * DD + d];
    for (int m = tid; m < NSLOTS; m += 256) rows[m] = b * TT + g_top[b * NSLOTS + m];
    __syncthreads();
    for (int m = wid; m < NSLOTS; m += 8) {
        long base = (long)rows[m] * DD;
        float s = 0.f;
        for (int d = lane; d < DD; d += 32) s += g_h[base + d] * qs[d];
        #pragma unroll
        for (int o = 16; o > 0; o >>= 1) s += __shfl_down_sync(0xffffffffu, s, o);
        if (lane == 0) sc[m] = s;
    }
    __syncthreads();
    float v = (tid < NSLOTS) ? sc[tid] : -1e30f;
    float vm = v;
    #pragma unroll
    for (int o = 16; o > 0; o >>= 1) vm = fmaxf(vm, __shfl_down_sync(0xffffffffu, vm, o));
    if ((tid & 31) == 0) red[tid >> 5] = vm;
    __syncthreads();
    if (tid < 32) {
        float x = (tid < 8) ? red[tid] : -1e30f;
        #pragma unroll
        for (int o = 16; o > 0; o >>= 1) x = fmaxf(x, __shfl_down_sync(0xffffffffu, x, o));
        if (tid == 0) red[0] = x;
    }
    __syncthreads();
    float mx = red[0];
    __syncthreads();
    float e = (tid < NSLOTS) ? expf(v - mx) : 0.f;
    float tot = block_reduce_sum(e, red);
    if (tid < NSLOTS) sc[tid] = e / tot;
    __syncthreads();
    for (int d = tid; d < DD; d += 256) {
        float s = 0.f;
        for (int m = 0; m < NSLOTS; m++)
            s += sc[m] * g_h[(long)rows[m] * DD + d];
        g_ctx[b * DD + d] = s;
    }
}

// ---------------- out = ctx @ out_W + out_b ----------------
__global__ void __launch_bounds__(256)
out_kernel(const float* __restrict__ oW, const float* __restrict__ ob,
           float* __restrict__ out) {
    __shared__ float cs[BB * DD];
    int tid = threadIdx.x;
    for (int i = tid; i < BB * DD; i += 256) cs[i] = g_ctx[i];
    __syncthreads();
    int v = blockIdx.x * 256 + tid;
    if (v >= VV) return;
    float acc[BB];
    #pragma unroll
    for (int b = 0; b < BB; b++) acc[b] = 0.f;
    for (int d = 0; d < DD; d++) {
        float w = oW[(long)d * VV + v];
        #pragma unroll
        for (int b = 0; b < BB; b++) acc[b] += cs[b * DD + d] * w;
    }
    float bias = ob[v];
    #pragma unroll
    for (int b = 0; b < BB; b++) out[(long)b * VV + v] = acc[b] + bias;
}

// ---------------- launch ----------------
extern "C" void kernel_launch(void* const* d_in, const int* in_sizes, int n_in,
                              void* d_out, int out_size) {
    const int*   seq   = (const int*)  d_in[0];
    const float* embed = (const float*)d_in[1];
    const float* W1    = (const float*)d_in[2];
    const float* b1    = (const float*)d_in[3];
    const float* W2    = (const float*)d_in[4];
    const float* b2    = (const float*)d_in[5];
    const float* ln_g  = (const float*)d_in[6];
    const float* ln_b  = (const float*)d_in[7];
    const float* gW    = (const float*)d_in[8];
    const float* gb    = (const float*)d_in[9];
    const float* qW    = (const float*)d_in[10];
    const float* qb    = (const float*)d_in[11];
    const float* oW    = (const float*)d_in[12];
    const float* ob    = (const float*)d_in[13];
    float* out = (float*)d_out;

    __nv_bfloat16 *h0h, *h0l, *a1h, *a1l, *w1th, *w1tl, *w2th, *w2tl;
    float *ff;
    cudaGetSymbolAddress((void**)&h0h,  g_h0h);
    cudaGetSymbolAddress((void**)&h0l,  g_h0l);
    cudaGetSymbolAddress((void**)&a1h,  g_a1h);
    cudaGetSymbolAddress((void**)&a1l,  g_a1l);
    cudaGetSymbolAddress((void**)&w1th, g_w1th);
    cudaGetSymbolAddress((void**)&w1tl, g_w1tl);
    cudaGetSymbolAddress((void**)&w2th, g_w2th);
    cudaGetSymbolAddress((void**)&w2tl, g_w2tl);
    cudaGetSymbolAddress((void**)&ff,   g_ff);

    // 0. weight transpose + split: W1 [512][1024] -> w1t [1024][512]; W2 [1024][512] -> w2t [512][1024]
    transpose_convert_kernel<<<dim3(2*DD/32, DD/32), dim3(32, 8)>>>(W1, w1th, w1tl, DD, 2*DD);
    transpose_convert_kernel<<<dim3(DD/32, 2*DD/32), dim3(32, 8)>>>(W2, w2th, w2tl, 2*DD, DD);

    // 1. embedding gather (+ bf16 split)
    {
        long total = (long)NTOK * (DD / 4);
        int blocks = (int)((total + 255) / 256);
        gather_kernel<<<blocks, 256>>>(seq, embed);
    }
    // 2. GEMM1: a1(hi/lo) = relu(h0 @ W1 + b1)   (M=32768, N=1024, K=512)
    mma_gemm_kernel<1><<<dim3(2*DD/128, NTOK/128), 256, GEMM_SMEM>>>(
        h0h, h0l, w1th, w1tl, b1, nullptr, a1h, a1l, NTOK, 2*DD, DD);
    // 3. GEMM2: ff = a1 @ W2 + b2                 (M=32768, N=512, K=1024)
    mma_gemm_kernel<0><<<dim3(DD/128, NTOK/128), 256, GEMM_SMEM>>>(
        a1h, a1l, w2th, w2tl, b2, ff, nullptr, nullptr, NTOK, DD, 2*DD);
    // 4. h = LN(h0 + ff)
    ln_kernel<<<NTOK, 256>>>(ln_g, ln_b);
    // 5. gate projections + windowed combine
    gatedot_kernel<<<NTOK / 8, 256>>>(gW);
    gatecomb_kernel<<<NTOK / 256, 256>>>(gb);
    // 6. top-256 per batch
    topk_kernel<<<BB, 512>>>();
    // 7. q projection
    q_kernel<<<BB, 256>>>(qW, qb);
    // 8. attention read
    attn_kernel<<<BB, 256>>>();
    // 9. vocab projection
    out_kernel<<<(VV + 255) / 256, 256>>>(oW, ob, out);

    (void)in_sizes; (void)n_in; (void)out_size;
}